// round 4
// baseline (speedup 1.0000x reference)
#include <cuda_runtime.h>
#include <cuda_bf16.h>

// x: (1, 256, 512, 512) fp32 -> out: (1, 64, 512, 512), mean over groups of 4 channels.
// HW = 512*512 = 262144 floats = 65536 float4 per channel.
// out[c][p] = 0.25 * (x[4c][p] + x[4c+1][p] + x[4c+2][p] + x[4c+3][p])

static constexpr int HW4 = (512 * 512) / 4;   // float4s per channel plane = 65536
static constexpr int C_OUT = 64;
static constexpr int THREADS = 256;

__global__ __launch_bounds__(THREADS)
void spectral_blurrin_kernel(const float4* __restrict__ x,
                             float4* __restrict__ out) {
    const int p = blockIdx.x * THREADS + threadIdx.x;   // position within plane (float4 units)
    const int c = blockIdx.y;                           // output channel

    const long long base = (long long)c * 4 * HW4 + p;  // first of 4 input channels

    // 4 independent 128-bit loads, 1 MB apart (distinct L2 partitions) -> MLP=4
    const float4 a = x[base];
    const float4 b = x[base + HW4];
    const float4 d = x[base + 2 * HW4];
    const float4 e = x[base + 3 * HW4];

    float4 r;
    r.x = (a.x + b.x + d.x + e.x) * 0.25f;
    r.y = (a.y + b.y + d.y + e.y) * 0.25f;
    r.z = (a.z + b.z + d.z + e.z) * 0.25f;
    r.w = (a.w + b.w + d.w + e.w) * 0.25f;

    out[(long long)c * HW4 + p] = r;
}

extern "C" void kernel_launch(void* const* d_in, const int* in_sizes, int n_in,
                              void* d_out, int out_size) {
    const float4* x = (const float4*)d_in[0];
    float4* out = (float4*)d_out;

    dim3 grid(HW4 / THREADS, C_OUT);   // (256, 64) = 16384 blocks
    spectral_blurrin_kernel<<<grid, THREADS>>>(x, out);
}